// round 9
// baseline (speedup 1.0000x reference)
#include <cuda_runtime.h>
#include <cuda_bf16.h>
#include <cstdint>

#define BB 4
#define NN 2048
#define DIMX 512
#define DHD 64
#define NKEY 2049
#define NKPAD 2304
#define MTOT (BB*NN)
typedef __nv_bfloat16 bf16;

// ---------------- scratch --------------------------------------------------
__device__ __align__(256) bf16 g_xn_hi[MTOT*DIMX];
__device__ __align__(256) bf16 g_xn_lo[MTOT*DIMX];
__device__ __align__(256) bf16 g_q_hi [MTOT*DIMX];
__device__ __align__(256) bf16 g_q_lo [MTOT*DIMX];
__device__ __align__(256) bf16 g_ao_hi[MTOT*DIMX];
__device__ __align__(256) bf16 g_ao_lo[MTOT*DIMX];
__device__ __align__(256) float g_o2  [MTOT*DIMX];
__device__ __align__(256) bf16 g_k_hi [BB*NKPAD*DHD];
__device__ __align__(256) bf16 g_k_lo [BB*NKPAD*DHD];
__device__ __align__(256) bf16 g_vt_hi[BB*DHD*NKPAD];
__device__ __align__(256) bf16 g_vt_lo[BB*DHD*NKPAD];
__device__ __align__(256) bf16 g_wq_hi[DIMX*DIMX];
__device__ __align__(256) bf16 g_wq_lo[DIMX*DIMX];
__device__ __align__(256) bf16 g_wk_hi[128*DIMX];
__device__ __align__(256) bf16 g_wk_lo[128*DIMX];
__device__ __align__(256) bf16 g_wo_hi[DIMX*DIMX];
__device__ __align__(256) bf16 g_wo_lo[DIMX*DIMX];
__device__ __align__(256) float g_mskf[BB*NKPAD];

// ---------------- helpers --------------------------------------------------
__device__ __forceinline__ uint32_t smem_u32(const void* p) {
    uint32_t a;
    asm("{ .reg .u64 t; cvta.to.shared.u64 t, %1; cvt.u32.u64 %0, t; }" : "=r"(a) : "l"(p));
    return a;
}
__device__ __forceinline__ void ldsm4(uint32_t (&r)[4], uint32_t a) {
    asm volatile("ldmatrix.sync.aligned.m8n8.x4.shared.b16 {%0,%1,%2,%3}, [%4];"
                 : "=r"(r[0]), "=r"(r[1]), "=r"(r[2]), "=r"(r[3]) : "r"(a));
}
__device__ __forceinline__ void ldsm2(uint32_t (&r)[2], uint32_t a) {
    asm volatile("ldmatrix.sync.aligned.m8n8.x2.shared.b16 {%0,%1}, [%2];"
                 : "=r"(r[0]), "=r"(r[1]) : "r"(a));
}
__device__ __forceinline__ void mma_bf(float (&d)[4], const uint32_t (&a)[4], const uint32_t (&b)[2]) {
    asm volatile("mma.sync.aligned.m16n8k16.row.col.f32.bf16.bf16.f32 "
                 "{%0,%1,%2,%3}, {%4,%5,%6,%7}, {%8,%9}, {%0,%1,%2,%3};"
                 : "+f"(d[0]), "+f"(d[1]), "+f"(d[2]), "+f"(d[3])
                 : "r"(a[0]), "r"(a[1]), "r"(a[2]), "r"(a[3]), "r"(b[0]), "r"(b[1]));
}
#define CP16(dst, src) asm volatile("cp.async.cg.shared.global [%0], [%1], 16;" :: "r"(dst), "l"(src) : "memory")
#define CP4(dst, src)  asm volatile("cp.async.ca.shared.global [%0], [%1], 4;"  :: "r"(dst), "l"(src) : "memory")
#define CP_COMMIT()    asm volatile("cp.async.commit_group;" ::: "memory")
#define CP_WAIT0()     asm volatile("cp.async.wait_group 0;" ::: "memory")
#define CP_WAIT1()     asm volatile("cp.async.wait_group 1;" ::: "memory")

__device__ __forceinline__ void split2(float v, bf16& h, bf16& l) {
    h = __float2bfloat16(v);
    l = __float2bfloat16(v - __bfloat162float(h));
}
__device__ __forceinline__ uint32_t packbf(bf16 a, bf16 b) {
    return (uint32_t)__bfloat16_as_ushort(a) | ((uint32_t)__bfloat16_as_ushort(b) << 16);
}
__device__ __forceinline__ void splitpack(float a, float b, uint32_t& hw, uint32_t& lw) {
    asm("cvt.rn.bf16x2.f32 %0, %2, %1;" : "=r"(hw) : "f"(a), "f"(b));
    float ha = __uint_as_float(hw << 16);
    float hb = __uint_as_float(hw & 0xFFFF0000u);
    float la = a - ha, lb = b - hb;
    asm("cvt.rn.bf16x2.f32 %0, %2, %1;" : "=r"(lw) : "f"(la), "f"(lb));
}

// ---------------- LayerNorm (SPLIT=1: bf16 hi/lo; 0: fp32) ----------------
template<int SPLIT>
__global__ __launch_bounds__(128) void ln_k(const float* __restrict__ x, const float* __restrict__ g,
                                            float* __restrict__ yf, bf16* __restrict__ yh, bf16* __restrict__ yl) {
    int row = blockIdx.x, t = threadIdx.x;
    float4 v = reinterpret_cast<const float4*>(x + (size_t)row*DIMX)[t];
    float s  = v.x + v.y + v.z + v.w;
    float s2 = v.x*v.x + v.y*v.y + v.z*v.z + v.w*v.w;
#pragma unroll
    for (int o = 16; o > 0; o >>= 1) {
        s  += __shfl_xor_sync(0xffffffffu, s,  o);
        s2 += __shfl_xor_sync(0xffffffffu, s2, o);
    }
    __shared__ float ws[4], ws2[4];
    int w = t >> 5;
    if ((t & 31) == 0) { ws[w] = s; ws2[w] = s2; }
    __syncthreads();
    float S = ws[0]+ws[1]+ws[2]+ws[3], S2 = ws2[0]+ws2[1]+ws2[2]+ws2[3];
    float mu = S * (1.0f/DIMX);
    float r = rsqrtf(S2*(1.0f/DIMX) - mu*mu + 1e-5f);
    float4 gg = reinterpret_cast<const float4*>(g)[t];
    float o0=(v.x-mu)*r*gg.x, o1=(v.y-mu)*r*gg.y, o2=(v.z-mu)*r*gg.z, o3=(v.w-mu)*r*gg.w;
    if (SPLIT == 0) {
        reinterpret_cast<float4*>(yf + (size_t)row*DIMX)[t] = make_float4(o0,o1,o2,o3);
    } else {
        uint2 hw, lw;
        splitpack(o0, o1, hw.x, lw.x);
        splitpack(o2, o3, hw.y, lw.y);
        *reinterpret_cast<uint2*>(yh + (size_t)row*DIMX + t*4) = hw;
        *reinterpret_cast<uint2*>(yl + (size_t)row*DIMX + t*4) = lw;
    }
}

// ---------------- weight transpose + split: W[k][N] -> hi/lo[n][k] ---------
__global__ void tsplit_k(const float* __restrict__ W, bf16* __restrict__ hi, bf16* __restrict__ lo, int N) {
    __shared__ float t[32][33];
    int n0 = blockIdx.x*32, k0 = blockIdx.y*32;
    int tx = threadIdx.x, ty = threadIdx.y;
    for (int r = ty; r < 32; r += 8) t[r][tx] = W[(size_t)(k0+r)*N + n0+tx];
    __syncthreads();
    for (int r = ty; r < 32; r += 8) {
        bf16 h, l; split2(t[tx][r], h, l);
        hi[(size_t)(n0+r)*DIMX + k0+tx] = h;
        lo[(size_t)(n0+r)*DIMX + k0+tx] = l;
    }
}

// ---------------- null kv + key padding + mask floats ----------------------
__global__ void kvinit_k(const float* __restrict__ nkv, const unsigned* __restrict__ mask) {
    int e = blockIdx.x*256 + threadIdx.x;
    if (e < 256) {
        int b = e >> 6, d = e & 63;
        bf16 h, l;
        split2(nkv[d], h, l);
        g_k_hi[(size_t)b*NKPAD*DHD + d] = h; g_k_lo[(size_t)b*NKPAD*DHD + d] = l;
        split2(nkv[64+d], h, l);
        g_vt_hi[((size_t)b*DHD+d)*NKPAD] = h; g_vt_lo[((size_t)b*DHD+d)*NKPAD] = l;
    }
    if (e < BB*255*DHD) {
        int b = e/(255*DHD), rem = e%(255*DHD);
        int key = 2049 + rem/DHD, d = rem % DHD;
        bf16 z = __float2bfloat16(0.f);
        g_k_hi [((size_t)b*NKPAD+key)*DHD + d] = z;
        g_k_lo [((size_t)b*NKPAD+key)*DHD + d] = z;
        g_vt_hi[((size_t)b*DHD+d)*NKPAD + key] = z;
        g_vt_lo[((size_t)b*DHD+d)*NKPAD + key] = z;
    }
    if (e < BB*NKPAD) {
        int b = e / NKPAD, jj = e % NKPAD;
        float v;
        if (jj == 0)         v = 1.f;
        else if (jj < NKEY)  v = (mask[(size_t)b*NN + jj - 1] != 0u) ? 1.f : 0.f;
        else                 v = 0.f;
        g_mskf[e] = v;
    }
}

// ---------------- mma.sync split-precision GEMM ----------------------------
#define LDA 40
template<int MODE>
__global__ __launch_bounds__(256,2) void gemm_mma(const bf16* __restrict__ Ah, const bf16* __restrict__ Al,
                                                  const bf16* __restrict__ Bh, const bf16* __restrict__ Bl,
                                                  float* __restrict__ C) {
    __shared__ bf16 At[128*LDA];
    __shared__ bf16 Bt[128*LDA];
    int tid = threadIdx.x, wid = tid >> 5, lane = tid & 31;
    int m0 = blockIdx.y*128, n0 = blockIdx.x*128;
    int wm = (wid & 3)*32, wn = (wid >> 2)*64;
    uint32_t sA = smem_u32(At), sB = smem_u32(Bt);
    int ldr = tid >> 1, ldc = (tid & 1)*16;
    int r16 = lane & 15, c8 = (lane >> 4) << 3, tt = lane & 15;

    float acc[2][8][4];
#pragma unroll
    for (int i = 0; i < 2; i++)
#pragma unroll
        for (int n = 0; n < 8; n++)
#pragma unroll
            for (int j = 0; j < 4; j++) acc[i][n][j] = 0.f;

    for (int term = 0; term < 3; term++) {
        const bf16* Ap = (term == 1) ? Al : Ah;
        const bf16* Bp = (term == 2) ? Bl : Bh;
        for (int k0 = 0; k0 < DIMX; k0 += 32) {
            __syncthreads();
            const uint4* ag = reinterpret_cast<const uint4*>(Ap + (size_t)(m0+ldr)*DIMX + k0 + ldc);
            const uint4* bg = reinterpret_cast<const uint4*>(Bp + (size_t)(n0+ldr)*DIMX + k0 + ldc);
            uint4 a0 = ag[0], a1 = ag[1], b0 = bg[0], b1 = bg[1];
            *reinterpret_cast<uint4*>((char*)At + ldr*80 + ldc*2)      = a0;
            *reinterpret_cast<uint4*>((char*)At + ldr*80 + ldc*2 + 16) = a1;
            *reinterpret_cast<uint4*>((char*)Bt + ldr*80 + ldc*2)      = b0;
            *reinterpret_cast<uint4*>((char*)Bt + ldr*80 + ldc*2 + 16) = b1;
            __syncthreads();
#pragma unroll
            for (int kk = 0; kk < 32; kk += 16) {
                uint32_t af0[4], af1[4];
                ldsm4(af0, sA + (uint32_t)((wm      + r16)*80 + (kk + c8)*2));
                ldsm4(af1, sA + (uint32_t)((wm + 16 + r16)*80 + (kk + c8)*2));
#pragma unroll
                for (int nf = 0; nf < 8; nf++) {
                    uint32_t bb[2];
                    ldsm2(bb, sB + (uint32_t)((wn + nf*8 + (tt & 7))*80 + (kk + ((tt >> 3) << 3))*2));
                    mma_bf(acc[0][nf], af0, bb);
                    mma_bf(acc[1][nf], af1, bb);
                }
            }
        }
    }

    int r4 = lane >> 2, c2 = (lane & 3)*2;
#pragma unroll
    for (int mf = 0; mf < 2; mf++) {
        int mA = m0 + wm + mf*16 + r4, mB = mA + 8;
#pragma unroll
        for (int nf = 0; nf < 8; nf++) {
            int nc = n0 + wn + nf*8 + c2;
            float v0 = acc[mf][nf][0], v1 = acc[mf][nf][1];
            float v2 = acc[mf][nf][2], v3 = acc[mf][nf][3];
            if (MODE == 0) {
                *reinterpret_cast<float2*>(C + (size_t)mA*DIMX + nc) = make_float2(v0, v1);
                *reinterpret_cast<float2*>(C + (size_t)mB*DIMX + nc) = make_float2(v2, v3);
            } else if (MODE == 1) {
                uint32_t hw, lw;
                splitpack(v0*0.125f, v1*0.125f, hw, lw);
                *reinterpret_cast<uint32_t*>(g_q_hi + (size_t)mA*DIMX + nc) = hw;
                *reinterpret_cast<uint32_t*>(g_q_lo + (size_t)mA*DIMX + nc) = lw;
                splitpack(v2*0.125f, v3*0.125f, hw, lw);
                *reinterpret_cast<uint32_t*>(g_q_hi + (size_t)mB*DIMX + nc) = hw;
                *reinterpret_cast<uint32_t*>(g_q_lo + (size_t)mB*DIMX + nc) = lw;
            } else {
                int bA = mA >> 11, keyA = 1 + (mA & 2047);
                int bB = mB >> 11, keyB = 1 + (mB & 2047);
                bf16 h0,h1,h2,h3,l0,l1,l2,l3;
                split2(v0,h0,l0); split2(v1,h1,l1); split2(v2,h2,l2); split2(v3,h3,l3);
                if (nc < DHD) {
                    *reinterpret_cast<uint32_t*>(g_k_hi + ((size_t)bA*NKPAD+keyA)*DHD + nc) = packbf(h0,h1);
                    *reinterpret_cast<uint32_t*>(g_k_lo + ((size_t)bA*NKPAD+keyA)*DHD + nc) = packbf(l0,l1);
                    *reinterpret_cast<uint32_t*>(g_k_hi + ((size_t)bB*NKPAD+keyB)*DHD + nc) = packbf(h2,h3);
                    *reinterpret_cast<uint32_t*>(g_k_lo + ((size_t)bB*NKPAD+keyB)*DHD + nc) = packbf(l2,l3);
                } else {
                    int d = nc - DHD;
                    g_vt_hi[((size_t)bA*DHD+d  )*NKPAD + keyA] = h0;
                    g_vt_hi[((size_t)bA*DHD+d+1)*NKPAD + keyA] = h1;
                    g_vt_lo[((size_t)bA*DHD+d  )*NKPAD + keyA] = l0;
                    g_vt_lo[((size_t)bA*DHD+d+1)*NKPAD + keyA] = l1;
                    g_vt_hi[((size_t)bB*DHD+d  )*NKPAD + keyB] = h2;
                    g_vt_hi[((size_t)bB*DHD+d+1)*NKPAD + keyB] = h3;
                    g_vt_lo[((size_t)bB*DHD+d  )*NKPAD + keyB] = l2;
                    g_vt_lo[((size_t)bB*DHD+d+1)*NKPAD + keyB] = l3;
                }
            }
        }
    }
}

// ---------------- mma.sync attention, 64-key tiles, 2 CTAs/SM --------------
// stage: K hi @0, K lo @9216, VT hi @18432, VT lo @27648 (each 64x144B),
// mask @36864 (256B). stage = 37120 B; two stages = 74240 B -> 2 CTAs/SM.
#define TK 64
#define STG 37120u
#define ATTN_SMEM (2*STG)
#define NT (NKPAD/TK)

__device__ __forceinline__ void attn_issue(uint32_t dstbase, int b, int t0, int tid) {
#pragma unroll
    for (int rep = 0; rep < 4; rep++) {
        int idx = rep*256 + tid;
        int mat = idx >> 9, row = (idx >> 3) & 63, ch = idx & 7;
        const bf16* src = (mat ? g_k_lo : g_k_hi) + ((size_t)b*NKPAD + t0*TK + row)*DHD + ch*8;
        CP16(dstbase + (uint32_t)(mat*9216 + row*144 + ch*16), src);
    }
#pragma unroll
    for (int rep = 0; rep < 4; rep++) {
        int idx = rep*256 + tid;
        int mat = idx >> 9, row = (idx >> 3) & 63, ch = idx & 7;
        const bf16* src = (mat ? g_vt_lo : g_vt_hi) + ((size_t)b*DHD + row)*NKPAD + t0*TK + ch*8;
        CP16(dstbase + 18432u + (uint32_t)(mat*9216 + row*144 + ch*16), src);
    }
    if (tid < TK) {
        const float* src = g_mskf + (size_t)b*NKPAD + t0*TK + tid;
        CP4(dstbase + 36864u + (uint32_t)(tid*4), src);
    }
    CP_COMMIT();
}

__global__ __launch_bounds__(256,2) void attn_mma(const unsigned* __restrict__ mask) {
    extern __shared__ __align__(128) char sm[];
    uint32_t sb = smem_u32(sm);
    int tid = threadIdx.x, wid = tid >> 5, lane = tid & 31;
    int m0 = blockIdx.x*128, h = blockIdx.y, b = blockIdx.z;
    int r16 = lane & 15, c8 = (lane >> 4) << 3, tt = lane & 15;

    // ---- stage Q hi/lo into both stages' K areas, pull frags to regs ----
#pragma unroll
    for (int rep = 0; rep < 8; rep++) {
        int idx = rep*256 + tid;
        int mat = idx >> 10, row = (idx >> 3) & 127, ch = idx & 7;
        const bf16* src = (mat ? g_q_lo : g_q_hi) + ((size_t)(b*NN + m0 + row))*DIMX + h*DHD + ch*8;
        *reinterpret_cast<uint4*>(sm + mat*18432 + row*144 + ch*16) =
            *reinterpret_cast<const uint4*>(src);
    }
    __syncthreads();
    uint32_t qh[4][4], ql[4][4];
#pragma unroll
    for (int k = 0; k < 4; k++) {
        ldsm4(qh[k], sb +         (uint32_t)((wid*16 + r16)*144 + (k*16 + c8)*2));
        ldsm4(ql[k], sb + 18432 + (uint32_t)((wid*16 + r16)*144 + (k*16 + c8)*2));
    }
    __syncthreads();

    float o[8][4];
#pragma unroll
    for (int n = 0; n < 8; n++)
#pragma unroll
        for (int j = 0; j < 4; j++) o[n][j] = 0.f;
    float lsum0 = 0.f, lsum1 = 0.f;

    attn_issue(sb, b, 0, tid);

    for (int t0 = 0; t0 < NT; t0++) {
        uint32_t stb = sb + (uint32_t)(t0 & 1)*STG;
        if (t0 < NT - 1) {
            attn_issue(sb + (uint32_t)((t0+1) & 1)*STG, b, t0+1, tid);
            CP_WAIT1();
        } else {
            CP_WAIT0();
        }
        __syncthreads();
        const float* msk = reinterpret_cast<const float*>(sm + (t0 & 1)*STG + 36864);

        // ---- S = Q K^T, 3-term split (64 keys -> nf 0..7) ----
        float s[8][4];
#pragma unroll
        for (int n = 0; n < 8; n++)
#pragma unroll
            for (int j = 0; j < 4; j++) s[n][j] = 0.f;
#pragma unroll
        for (int k = 0; k < 4; k++) {
#pragma unroll
            for (int nf = 0; nf < 8; nf++) {
                uint32_t bh[2], bl[2];
                uint32_t off = (uint32_t)((nf*8 + (tt & 7))*144 + (k*16 + ((tt >> 3) << 3))*2);
                ldsm2(bh, stb + off);
                mma_bf(s[nf], qh[k], bh);
                mma_bf(s[nf], ql[k], bh);
                ldsm2(bl, stb + 9216 + off);
                mma_bf(s[nf], qh[k], bl);
            }
        }

        // ---- softmax (MUFU exp; no max subtraction) ----
#pragma unroll
        for (int nf = 0; nf < 8; nf++) {
            int colb = nf*8 + 2*(lane & 3);
            float m0f = msk[colb], m1f = msk[colb + 1];
            float p0 = __expf(s[nf][0]) * m0f;
            float p1 = __expf(s[nf][1]) * m1f;
            float p2 = __expf(s[nf][2]) * m0f;
            float p3 = __expf(s[nf][3]) * m1f;
            s[nf][0] = p0; s[nf][1] = p1; s[nf][2] = p2; s[nf][3] = p3;
            lsum0 += p0 + p1; lsum1 += p2 + p3;
        }

        // ---- O += P V, 3-term split (4 k-frags of 16 keys) ----
#pragma unroll
        for (int kt = 0; kt < 4; kt++) {
            uint32_t ph[4], pl[4];
            splitpack(s[2*kt  ][0], s[2*kt  ][1], ph[0], pl[0]);
            splitpack(s[2*kt  ][2], s[2*kt  ][3], ph[1], pl[1]);
            splitpack(s[2*kt+1][0], s[2*kt+1][1], ph[2], pl[2]);
            splitpack(s[2*kt+1][2], s[2*kt+1][3], ph[3], pl[3]);
#pragma unroll
            for (int nf = 0; nf < 8; nf++) {
                uint32_t vh[2], vl[2];
                uint32_t off = (uint32_t)((nf*8 + (tt & 7))*144 + (kt*16 + ((tt >> 3) << 3))*2);
                ldsm2(vh, stb + 18432 + off);
                mma_bf(o[nf], ph, vh);
                mma_bf(o[nf], pl, vh);
                ldsm2(vl, stb + 27648 + off);
                mma_bf(o[nf], ph, vl);
            }
        }
        __syncthreads();
    }

    // ---- finalize ----
    lsum0 += __shfl_xor_sync(0xffffffffu, lsum0, 1);
    lsum0 += __shfl_xor_sync(0xffffffffu, lsum0, 2);
    lsum1 += __shfl_xor_sync(0xffffffffu, lsum1, 1);
    lsum1 += __shfl_xor_sync(0xffffffffu, lsum1, 2);
    float inv0 = 1.f / lsum0, inv1 = 1.f / lsum1;
    size_t rowA = (size_t)(b*NN + m0 + wid*16 + (lane >> 2));
    size_t rowB = rowA + 8;
    int colb = h*DHD + 2*(lane & 3);
#pragma unroll
    for (int nf = 0; nf < 8; nf++) {
        int nc = colb + nf*8;
        uint32_t hw, lw;
        splitpack(o[nf][0]*inv0, o[nf][1]*inv0, hw, lw);
        *reinterpret_cast<uint32_t*>(g_ao_hi + rowA*DIMX + nc) = hw;
        *reinterpret_cast<uint32_t*>(g_ao_lo + rowA*DIMX + nc) = lw;
        splitpack(o[nf][2]*inv1, o[nf][3]*inv1, hw, lw);
        *reinterpret_cast<uint32_t*>(g_ao_hi + rowB*DIMX + nc) = hw;
        *reinterpret_cast<uint32_t*>(g_ao_lo + rowB*DIMX + nc) = lw;
    }
}

// ---------------- launch ----------------------------------------------------
extern "C" void kernel_launch(void* const* d_in, const int* in_sizes, int n_in,
                              void* d_out, int out_size) {
    const float*    x      = (const float*)d_in[0];
    const unsigned* mask   = (const unsigned*)d_in[1];
    const float*    gamma  = (const float*)d_in[2];
    const float*    Wq     = (const float*)d_in[3];
    const float*    Wkv    = (const float*)d_in[4];
    const float*    nkv    = (const float*)d_in[5];
    const float*    Wout   = (const float*)d_in[6];
    const float*    ogamma = (const float*)d_in[7];
    float*          out    = (float*)d_out;

    float *o2;
    bf16 *xnh, *xnl, *wqh, *wql, *wkh, *wkl, *woh, *wol, *aoh, *aol;
    cudaGetSymbolAddress((void**)&o2,  g_o2);
    cudaGetSymbolAddress((void**)&xnh, g_xn_hi); cudaGetSymbolAddress((void**)&xnl, g_xn_lo);
    cudaGetSymbolAddress((void**)&wqh, g_wq_hi); cudaGetSymbolAddress((void**)&wql, g_wq_lo);
    cudaGetSymbolAddress((void**)&wkh, g_wk_hi); cudaGetSymbolAddress((void**)&wkl, g_wk_lo);
    cudaGetSymbolAddress((void**)&woh, g_wo_hi); cudaGetSymbolAddress((void**)&wol, g_wo_lo);
    cudaGetSymbolAddress((void**)&aoh, g_ao_hi); cudaGetSymbolAddress((void**)&aol, g_ao_lo);
    cudaFuncSetAttribute(attn_mma, cudaFuncAttributeMaxDynamicSharedMemorySize, ATTN_SMEM);

    ln_k<1><<<MTOT, 128>>>(x, gamma, nullptr, xnh, xnl);
    tsplit_k<<<dim3(16,16), dim3(32,8)>>>(Wq,   wqh, wql, 512);
    tsplit_k<<<dim3(4, 16), dim3(32,8)>>>(Wkv,  wkh, wkl, 128);
    tsplit_k<<<dim3(16,16), dim3(32,8)>>>(Wout, woh, wol, 512);
    kvinit_k<<<255, 256>>>(nkv, mask);
    gemm_mma<1><<<dim3(4,64), 256>>>(xnh, xnl, wqh, wql, nullptr);
    gemm_mma<2><<<dim3(1,64), 256>>>(xnh, xnl, wkh, wkl, nullptr);
    attn_mma<<<dim3(16,8,4), 256, ATTN_SMEM>>>(mask);
    gemm_mma<0><<<dim3(4,64), 256>>>(aoh, aol, woh, wol, o2);
    ln_k<0><<<MTOT, 128>>>(o2, ogamma, out, nullptr, nullptr);
}

// round 10
// speedup vs baseline: 1.8917x; 1.8917x over previous
#include <cuda_runtime.h>
#include <cuda_bf16.h>
#include <cuda_fp16.h>
#include <cstdint>

#define BB 4
#define NN 2048
#define DIMX 512
#define DHD 64
#define NKEY 2049
#define NKPAD 2304
#define MTOT (BB*NN)
typedef __nv_bfloat16 bf16;

// ---------------- scratch --------------------------------------------------
__device__ __align__(256) bf16 g_xn_hi[MTOT*DIMX];
__device__ __align__(256) bf16 g_xn_lo[MTOT*DIMX];
__device__ __align__(256) half g_qf  [MTOT*DIMX];          // fp16 single-term Q
__device__ __align__(256) bf16 g_ao_hi[MTOT*DIMX];
__device__ __align__(256) bf16 g_ao_lo[MTOT*DIMX];
__device__ __align__(256) float g_o2  [MTOT*DIMX];
__device__ __align__(256) half g_kf  [BB*NKPAD*DHD];       // fp16 single-term K
__device__ __align__(256) bf16 g_vt_hi[BB*DHD*NKPAD];
__device__ __align__(256) bf16 g_vt_lo[BB*DHD*NKPAD];
__device__ __align__(256) bf16 g_wq_hi[DIMX*DIMX];
__device__ __align__(256) bf16 g_wq_lo[DIMX*DIMX];
__device__ __align__(256) bf16 g_wk_hi[128*DIMX];
__device__ __align__(256) bf16 g_wk_lo[128*DIMX];
__device__ __align__(256) bf16 g_wo_hi[DIMX*DIMX];
__device__ __align__(256) bf16 g_wo_lo[DIMX*DIMX];
__device__ __align__(256) float g_mskf[BB*NKPAD];

// ---------------- helpers --------------------------------------------------
__device__ __forceinline__ uint32_t smem_u32(const void* p) {
    uint32_t a;
    asm("{ .reg .u64 t; cvta.to.shared.u64 t, %1; cvt.u32.u64 %0, t; }" : "=r"(a) : "l"(p));
    return a;
}
__device__ __forceinline__ void ldsm4(uint32_t (&r)[4], uint32_t a) {
    asm volatile("ldmatrix.sync.aligned.m8n8.x4.shared.b16 {%0,%1,%2,%3}, [%4];"
                 : "=r"(r[0]), "=r"(r[1]), "=r"(r[2]), "=r"(r[3]) : "r"(a));
}
__device__ __forceinline__ void ldsm2(uint32_t (&r)[2], uint32_t a) {
    asm volatile("ldmatrix.sync.aligned.m8n8.x2.shared.b16 {%0,%1}, [%2];"
                 : "=r"(r[0]), "=r"(r[1]) : "r"(a));
}
__device__ __forceinline__ void mma_bf(float (&d)[4], const uint32_t (&a)[4], const uint32_t (&b)[2]) {
    asm volatile("mma.sync.aligned.m16n8k16.row.col.f32.bf16.bf16.f32 "
                 "{%0,%1,%2,%3}, {%4,%5,%6,%7}, {%8,%9}, {%0,%1,%2,%3};"
                 : "+f"(d[0]), "+f"(d[1]), "+f"(d[2]), "+f"(d[3])
                 : "r"(a[0]), "r"(a[1]), "r"(a[2]), "r"(a[3]), "r"(b[0]), "r"(b[1]));
}
__device__ __forceinline__ void mma_f16(float (&d)[4], const uint32_t (&a)[4], const uint32_t (&b)[2]) {
    asm volatile("mma.sync.aligned.m16n8k16.row.col.f32.f16.f16.f32 "
                 "{%0,%1,%2,%3}, {%4,%5,%6,%7}, {%8,%9}, {%0,%1,%2,%3};"
                 : "+f"(d[0]), "+f"(d[1]), "+f"(d[2]), "+f"(d[3])
                 : "r"(a[0]), "r"(a[1]), "r"(a[2]), "r"(a[3]), "r"(b[0]), "r"(b[1]));
}
#define CP16(dst, src) asm volatile("cp.async.cg.shared.global [%0], [%1], 16;" :: "r"(dst), "l"(src) : "memory")
#define CP4(dst, src)  asm volatile("cp.async.ca.shared.global [%0], [%1], 4;"  :: "r"(dst), "l"(src) : "memory")
#define CP_COMMIT()    asm volatile("cp.async.commit_group;" ::: "memory")
#define CP_WAIT0()     asm volatile("cp.async.wait_group 0;" ::: "memory")
#define CP_WAIT1()     asm volatile("cp.async.wait_group 1;" ::: "memory")

__device__ __forceinline__ void split2(float v, bf16& h, bf16& l) {
    h = __float2bfloat16(v);
    l = __float2bfloat16(v - __bfloat162float(h));
}
__device__ __forceinline__ uint32_t packbf(bf16 a, bf16 b) {
    return (uint32_t)__bfloat16_as_ushort(a) | ((uint32_t)__bfloat16_as_ushort(b) << 16);
}
__device__ __forceinline__ uint32_t packh2(float a, float b) {   // a -> low half
    uint32_t r;
    asm("cvt.rn.f16x2.f32 %0, %2, %1;" : "=r"(r) : "f"(a), "f"(b));
    return r;
}
__device__ __forceinline__ void splitpack(float a, float b, uint32_t& hw, uint32_t& lw) {
    asm("cvt.rn.bf16x2.f32 %0, %2, %1;" : "=r"(hw) : "f"(a), "f"(b));
    float ha = __uint_as_float(hw << 16);
    float hb = __uint_as_float(hw & 0xFFFF0000u);
    float la = a - ha, lb = b - hb;
    asm("cvt.rn.bf16x2.f32 %0, %2, %1;" : "=r"(lw) : "f"(la), "f"(lb));
}

// ---------------- LayerNorm (SPLIT=1: bf16 hi/lo; 0: fp32) ----------------
template<int SPLIT>
__global__ __launch_bounds__(128) void ln_k(const float* __restrict__ x, const float* __restrict__ g,
                                            float* __restrict__ yf, bf16* __restrict__ yh, bf16* __restrict__ yl) {
    int row = blockIdx.x, t = threadIdx.x;
    float4 v = reinterpret_cast<const float4*>(x + (size_t)row*DIMX)[t];
    float s  = v.x + v.y + v.z + v.w;
    float s2 = v.x*v.x + v.y*v.y + v.z*v.z + v.w*v.w;
#pragma unroll
    for (int o = 16; o > 0; o >>= 1) {
        s  += __shfl_xor_sync(0xffffffffu, s,  o);
        s2 += __shfl_xor_sync(0xffffffffu, s2, o);
    }
    __shared__ float ws[4], ws2[4];
    int w = t >> 5;
    if ((t & 31) == 0) { ws[w] = s; ws2[w] = s2; }
    __syncthreads();
    float S = ws[0]+ws[1]+ws[2]+ws[3], S2 = ws2[0]+ws2[1]+ws2[2]+ws2[3];
    float mu = S * (1.0f/DIMX);
    float r = rsqrtf(S2*(1.0f/DIMX) - mu*mu + 1e-5f);
    float4 gg = reinterpret_cast<const float4*>(g)[t];
    float o0=(v.x-mu)*r*gg.x, o1=(v.y-mu)*r*gg.y, o2=(v.z-mu)*r*gg.z, o3=(v.w-mu)*r*gg.w;
    if (SPLIT == 0) {
        reinterpret_cast<float4*>(yf + (size_t)row*DIMX)[t] = make_float4(o0,o1,o2,o3);
    } else {
        uint2 hw, lw;
        splitpack(o0, o1, hw.x, lw.x);
        splitpack(o2, o3, hw.y, lw.y);
        *reinterpret_cast<uint2*>(yh + (size_t)row*DIMX + t*4) = hw;
        *reinterpret_cast<uint2*>(yl + (size_t)row*DIMX + t*4) = lw;
    }
}

// ---------------- weight transpose + split: W[k][N] -> hi/lo[n][k] ---------
__global__ void tsplit_k(const float* __restrict__ W, bf16* __restrict__ hi, bf16* __restrict__ lo, int N) {
    __shared__ float t[32][33];
    int n0 = blockIdx.x*32, k0 = blockIdx.y*32;
    int tx = threadIdx.x, ty = threadIdx.y;
    for (int r = ty; r < 32; r += 8) t[r][tx] = W[(size_t)(k0+r)*N + n0+tx];
    __syncthreads();
    for (int r = ty; r < 32; r += 8) {
        bf16 h, l; split2(t[tx][r], h, l);
        hi[(size_t)(n0+r)*DIMX + k0+tx] = h;
        lo[(size_t)(n0+r)*DIMX + k0+tx] = l;
    }
}

// ---------------- null kv + key padding + mask floats ----------------------
__global__ void kvinit_k(const float* __restrict__ nkv, const unsigned* __restrict__ mask) {
    int e = blockIdx.x*256 + threadIdx.x;
    if (e < 256) {
        int b = e >> 6, d = e & 63;
        g_kf[(size_t)b*NKPAD*DHD + d] = __float2half(nkv[d]);
        bf16 h, l;
        split2(nkv[64+d], h, l);
        g_vt_hi[((size_t)b*DHD+d)*NKPAD] = h; g_vt_lo[((size_t)b*DHD+d)*NKPAD] = l;
    }
    if (e < BB*255*DHD) {
        int b = e/(255*DHD), rem = e%(255*DHD);
        int key = 2049 + rem/DHD, d = rem % DHD;
        bf16 z = __float2bfloat16(0.f);
        g_kf[((size_t)b*NKPAD+key)*DHD + d] = __float2half(0.f);
        g_vt_hi[((size_t)b*DHD+d)*NKPAD + key] = z;
        g_vt_lo[((size_t)b*DHD+d)*NKPAD + key] = z;
    }
    if (e < BB*NKPAD) {
        int b = e / NKPAD, jj = e % NKPAD;
        float v;
        if (jj == 0)         v = 1.f;
        else if (jj < NKEY)  v = (mask[(size_t)b*NN + jj - 1] != 0u) ? 1.f : 0.f;
        else                 v = 0.f;
        g_mskf[e] = v;
    }
}

// ---------------- mma.sync split-precision GEMM ----------------------------
#define LDA 40
template<int MODE>
__global__ __launch_bounds__(256,2) void gemm_mma(const bf16* __restrict__ Ah, const bf16* __restrict__ Al,
                                                  const bf16* __restrict__ Bh, const bf16* __restrict__ Bl,
                                                  float* __restrict__ C) {
    __shared__ bf16 At[128*LDA];
    __shared__ bf16 Bt[128*LDA];
    int tid = threadIdx.x, wid = tid >> 5, lane = tid & 31;
    int m0 = blockIdx.y*128, n0 = blockIdx.x*128;
    int wm = (wid & 3)*32, wn = (wid >> 2)*64;
    uint32_t sA = smem_u32(At), sB = smem_u32(Bt);
    int ldr = tid >> 1, ldc = (tid & 1)*16;
    int r16 = lane & 15, c8 = (lane >> 4) << 3, tt = lane & 15;

    float acc[2][8][4];
#pragma unroll
    for (int i = 0; i < 2; i++)
#pragma unroll
        for (int n = 0; n < 8; n++)
#pragma unroll
            for (int j = 0; j < 4; j++) acc[i][n][j] = 0.f;

    for (int term = 0; term < 3; term++) {
        const bf16* Ap = (term == 1) ? Al : Ah;
        const bf16* Bp = (term == 2) ? Bl : Bh;
        for (int k0 = 0; k0 < DIMX; k0 += 32) {
            __syncthreads();
            const uint4* ag = reinterpret_cast<const uint4*>(Ap + (size_t)(m0+ldr)*DIMX + k0 + ldc);
            const uint4* bg = reinterpret_cast<const uint4*>(Bp + (size_t)(n0+ldr)*DIMX + k0 + ldc);
            uint4 a0 = ag[0], a1 = ag[1], b0 = bg[0], b1 = bg[1];
            *reinterpret_cast<uint4*>((char*)At + ldr*80 + ldc*2)      = a0;
            *reinterpret_cast<uint4*>((char*)At + ldr*80 + ldc*2 + 16) = a1;
            *reinterpret_cast<uint4*>((char*)Bt + ldr*80 + ldc*2)      = b0;
            *reinterpret_cast<uint4*>((char*)Bt + ldr*80 + ldc*2 + 16) = b1;
            __syncthreads();
#pragma unroll
            for (int kk = 0; kk < 32; kk += 16) {
                uint32_t af0[4], af1[4];
                ldsm4(af0, sA + (uint32_t)((wm      + r16)*80 + (kk + c8)*2));
                ldsm4(af1, sA + (uint32_t)((wm + 16 + r16)*80 + (kk + c8)*2));
#pragma unroll
                for (int nf = 0; nf < 8; nf++) {
                    uint32_t bb[2];
                    ldsm2(bb, sB + (uint32_t)((wn + nf*8 + (tt & 7))*80 + (kk + ((tt >> 3) << 3))*2));
                    mma_bf(acc[0][nf], af0, bb);
                    mma_bf(acc[1][nf], af1, bb);
                }
            }
        }
    }

    int r4 = lane >> 2, c2 = (lane & 3)*2;
#pragma unroll
    for (int mf = 0; mf < 2; mf++) {
        int mA = m0 + wm + mf*16 + r4, mB = mA + 8;
#pragma unroll
        for (int nf = 0; nf < 8; nf++) {
            int nc = n0 + wn + nf*8 + c2;
            float v0 = acc[mf][nf][0], v1 = acc[mf][nf][1];
            float v2 = acc[mf][nf][2], v3 = acc[mf][nf][3];
            if (MODE == 0) {
                *reinterpret_cast<float2*>(C + (size_t)mA*DIMX + nc) = make_float2(v0, v1);
                *reinterpret_cast<float2*>(C + (size_t)mB*DIMX + nc) = make_float2(v2, v3);
            } else if (MODE == 1) {
                *reinterpret_cast<uint32_t*>(g_qf + (size_t)mA*DIMX + nc) = packh2(v0*0.125f, v1*0.125f);
                *reinterpret_cast<uint32_t*>(g_qf + (size_t)mB*DIMX + nc) = packh2(v2*0.125f, v3*0.125f);
            } else {
                int bA = mA >> 11, keyA = 1 + (mA & 2047);
                int bB = mB >> 11, keyB = 1 + (mB & 2047);
                if (nc < DHD) {
                    *reinterpret_cast<uint32_t*>(g_kf + ((size_t)bA*NKPAD+keyA)*DHD + nc) = packh2(v0, v1);
                    *reinterpret_cast<uint32_t*>(g_kf + ((size_t)bB*NKPAD+keyB)*DHD + nc) = packh2(v2, v3);
                } else {
                    int d = nc - DHD;
                    bf16 h0,h1,h2,h3,l0,l1,l2,l3;
                    split2(v0,h0,l0); split2(v1,h1,l1); split2(v2,h2,l2); split2(v3,h3,l3);
                    g_vt_hi[((size_t)bA*DHD+d  )*NKPAD + keyA] = h0;
                    g_vt_hi[((size_t)bA*DHD+d+1)*NKPAD + keyA] = h1;
                    g_vt_lo[((size_t)bA*DHD+d  )*NKPAD + keyA] = l0;
                    g_vt_lo[((size_t)bA*DHD+d+1)*NKPAD + keyA] = l1;
                    g_vt_hi[((size_t)bB*DHD+d  )*NKPAD + keyB] = h2;
                    g_vt_hi[((size_t)bB*DHD+d+1)*NKPAD + keyB] = h3;
                    g_vt_lo[((size_t)bB*DHD+d  )*NKPAD + keyB] = l2;
                    g_vt_lo[((size_t)bB*DHD+d+1)*NKPAD + keyB] = l3;
                }
            }
        }
    }
}

// ---------------- attention: fp16 single-term S, bf16 3-term PV ------------
// stage: Kf [128][144B] @0 (18432), VTh [64][272B] @18432 (17408),
// VTl @35840 (17408), mask @53248 (512). STG=53760; double-buffered.
#define STG 53760u
#define ATTN_SMEM (2*STG)

__device__ __forceinline__ void attn_issue(uint32_t dstbase, int b, int t0, int tid) {
#pragma unroll
    for (int rep = 0; rep < 4; rep++) {                    // Kf: 128 rows x 128B
        int idx = rep*256 + tid;
        int row = idx >> 3, ch = idx & 7;
        const half* src = g_kf + ((size_t)b*NKPAD + t0*128 + row)*DHD + ch*8;
        CP16(dstbase + (uint32_t)(row*144 + ch*16), src);
    }
#pragma unroll
    for (int rep = 0; rep < 8; rep++) {                    // VT hi/lo: 64 rows x 256B
        int idx = rep*256 + tid;
        int mat = idx >> 10, row = (idx >> 4) & 63, ch = idx & 15;
        const bf16* src = (mat ? g_vt_lo : g_vt_hi) + ((size_t)b*DHD + row)*NKPAD + t0*128 + ch*8;
        CP16(dstbase + 18432u + (uint32_t)(mat*17408 + row*272 + ch*16), src);
    }
    if (tid < 128) {
        const float* src = g_mskf + (size_t)b*NKPAD + t0*128 + tid;
        CP4(dstbase + 53248u + (uint32_t)(tid*4), src);
    }
    CP_COMMIT();
}

__global__ __launch_bounds__(256,1) void attn_mma(const unsigned* __restrict__ mask) {
    extern __shared__ __align__(128) char sm[];
    uint32_t sb = smem_u32(sm);
    int tid = threadIdx.x, wid = tid >> 5, lane = tid & 31;
    int m0 = blockIdx.x*128, h = blockIdx.y, b = blockIdx.z;
    int r16 = lane & 15, c8 = (lane >> 4) << 3, tt = lane & 15;

    // ---- stage Q (fp16) into stage-0 Kf region, pull frags to regs ----
#pragma unroll
    for (int rep = 0; rep < 4; rep++) {
        int idx = rep*256 + tid;
        int row = idx >> 3, ch = idx & 7;
        const half* src = g_qf + ((size_t)(b*NN + m0 + row))*DIMX + h*DHD + ch*8;
        *reinterpret_cast<uint4*>(sm + row*144 + ch*16) = *reinterpret_cast<const uint4*>(src);
    }
    __syncthreads();
    uint32_t qf[4][4];
#pragma unroll
    for (int k = 0; k < 4; k++)
        ldsm4(qf[k], sb + (uint32_t)((wid*16 + r16)*144 + (k*16 + c8)*2));
    __syncthreads();

    float o[8][4];
#pragma unroll
    for (int n = 0; n < 8; n++)
#pragma unroll
        for (int j = 0; j < 4; j++) o[n][j] = 0.f;
    float lsum0 = 0.f, lsum1 = 0.f;

    attn_issue(sb, b, 0, tid);

    for (int t0 = 0; t0 < NKPAD/128; t0++) {
        uint32_t stb = sb + (uint32_t)(t0 & 1)*STG;
        if (t0 < NKPAD/128 - 1) {
            attn_issue(sb + (uint32_t)((t0+1) & 1)*STG, b, t0+1, tid);
            CP_WAIT1();
        } else {
            CP_WAIT0();
        }
        __syncthreads();
        const float* msk = reinterpret_cast<const float*>(sm + (t0 & 1)*STG + 53248);

        // ---- S = Q K^T, single fp16 term ----
        float s[16][4];
#pragma unroll
        for (int n = 0; n < 16; n++)
#pragma unroll
            for (int j = 0; j < 4; j++) s[n][j] = 0.f;
#pragma unroll
        for (int k = 0; k < 4; k++) {
#pragma unroll
            for (int nf = 0; nf < 16; nf++) {
                uint32_t kb[2];
                ldsm2(kb, stb + (uint32_t)((nf*8 + (tt & 7))*144 + (k*16 + ((tt >> 3) << 3))*2));
                mma_f16(s[nf], qf[k], kb);
            }
        }

        // ---- softmax (MUFU exp; no max subtraction) ----
#pragma unroll
        for (int nf = 0; nf < 16; nf++) {
            int colb = nf*8 + 2*(lane & 3);
            float m0f = msk[colb], m1f = msk[colb + 1];
            float p0 = __expf(s[nf][0]) * m0f;
            float p1 = __expf(s[nf][1]) * m1f;
            float p2 = __expf(s[nf][2]) * m0f;
            float p3 = __expf(s[nf][3]) * m1f;
            s[nf][0] = p0; s[nf][1] = p1; s[nf][2] = p2; s[nf][3] = p3;
            lsum0 += p0 + p1; lsum1 += p2 + p3;
        }

        // ---- O += P V, 3-term bf16 split ----
#pragma unroll
        for (int kt = 0; kt < 8; kt++) {
            uint32_t ph[4], pl[4];
            splitpack(s[2*kt  ][0], s[2*kt  ][1], ph[0], pl[0]);
            splitpack(s[2*kt  ][2], s[2*kt  ][3], ph[1], pl[1]);
            splitpack(s[2*kt+1][0], s[2*kt+1][1], ph[2], pl[2]);
            splitpack(s[2*kt+1][2], s[2*kt+1][3], ph[3], pl[3]);
#pragma unroll
            for (int nf = 0; nf < 8; nf++) {
                uint32_t vh[2], vl[2];
                uint32_t off = (uint32_t)((nf*8 + (tt & 7))*272 + (kt*16 + ((tt >> 3) << 3))*2);
                ldsm2(vh, stb + 18432 + off);
                mma_bf(o[nf], ph, vh);
                mma_bf(o[nf], pl, vh);
                ldsm2(vl, stb + 35840 + off);
                mma_bf(o[nf], ph, vl);
            }
        }
        __syncthreads();
    }

    // ---- finalize ----
    lsum0 += __shfl_xor_sync(0xffffffffu, lsum0, 1);
    lsum0 += __shfl_xor_sync(0xffffffffu, lsum0, 2);
    lsum1 += __shfl_xor_sync(0xffffffffu, lsum1, 1);
    lsum1 += __shfl_xor_sync(0xffffffffu, lsum1, 2);
    float inv0 = 1.f / lsum0, inv1 = 1.f / lsum1;
    size_t rowA = (size_t)(b*NN + m0 + wid*16 + (lane >> 2));
    size_t rowB = rowA + 8;
    int colb = h*DHD + 2*(lane & 3);
#pragma unroll
    for (int nf = 0; nf < 8; nf++) {
        int nc = colb + nf*8;
        uint32_t hw, lw;
        splitpack(o[nf][0]*inv0, o[nf][1]*inv0, hw, lw);
        *reinterpret_cast<uint32_t*>(g_ao_hi + rowA*DIMX + nc) = hw;
        *reinterpret_cast<uint32_t*>(g_ao_lo + rowA*DIMX + nc) = lw;
        splitpack(o[nf][2]*inv1, o[nf][3]*inv1, hw, lw);
        *reinterpret_cast<uint32_t*>(g_ao_hi + rowB*DIMX + nc) = hw;
        *reinterpret_cast<uint32_t*>(g_ao_lo + rowB*DIMX + nc) = lw;
    }
}

// ---------------- launch ----------------------------------------------------
extern "C" void kernel_launch(void* const* d_in, const int* in_sizes, int n_in,
                              void* d_out, int out_size) {
    const float*    x      = (const float*)d_in[0];
    const unsigned* mask   = (const unsigned*)d_in[1];
    const float*    gamma  = (const float*)d_in[2];
    const float*    Wq     = (const float*)d_in[3];
    const float*    Wkv    = (const float*)d_in[4];
    const float*    nkv    = (const float*)d_in[5];
    const float*    Wout   = (const float*)d_in[6];
    const float*    ogamma = (const float*)d_in[7];
    float*          out    = (float*)d_out;

    float *o2;
    bf16 *xnh, *xnl, *wqh, *wql, *wkh, *wkl, *woh, *wol, *aoh, *aol;
    cudaGetSymbolAddress((void**)&o2,  g_o2);
    cudaGetSymbolAddress((void**)&xnh, g_xn_hi); cudaGetSymbolAddress((void**)&xnl, g_xn_lo);
    cudaGetSymbolAddress((void**)&wqh, g_wq_hi); cudaGetSymbolAddress((void**)&wql, g_wq_lo);
    cudaGetSymbolAddress((void**)&wkh, g_wk_hi); cudaGetSymbolAddress((void**)&wkl, g_wk_lo);
    cudaGetSymbolAddress((void**)&woh, g_wo_hi); cudaGetSymbolAddress((void**)&wol, g_wo_lo);
    cudaGetSymbolAddress((void**)&aoh, g_ao_hi); cudaGetSymbolAddress((void**)&aol, g_ao_lo);
    cudaFuncSetAttribute(attn_mma, cudaFuncAttributeMaxDynamicSharedMemorySize, ATTN_SMEM);

    ln_k<1><<<MTOT, 128>>>(x, gamma, nullptr, xnh, xnl);
    tsplit_k<<<dim3(16,16), dim3(32,8)>>>(Wq,   wqh, wql, 512);
    tsplit_k<<<dim3(4, 16), dim3(32,8)>>>(Wkv,  wkh, wkl, 128);
    tsplit_k<<<dim3(16,16), dim3(32,8)>>>(Wout, woh, wol, 512);
    kvinit_k<<<255, 256>>>(nkv, mask);
    gemm_mma<1><<<dim3(4,64), 256>>>(xnh, xnl, wqh, wql, nullptr);
    gemm_mma<2><<<dim3(1,64), 256>>>(xnh, xnl, wkh, wkl, nullptr);
    attn_mma<<<dim3(16,8,4), 256, ATTN_SMEM>>>(mask);
    gemm_mma<0><<<dim3(4,64), 256>>>(aoh, aol, woh, wol, o2);
    ln_k<0><<<MTOT, 128>>>(o2, ogamma, out, nullptr, nullptr);
}

// round 14
// speedup vs baseline: 2.3932x; 1.2651x over previous
#include <cuda_runtime.h>
#include <cuda_bf16.h>
#include <cuda_fp16.h>
#include <cstdint>

#define BB 4
#define NN 2048
#define DIMX 512
#define DHD 64
#define NKEY 2049
#define NKPAD 2304
#define MTOT (BB*NN)
typedef __nv_bfloat16 bf16;

// ---------------- scratch --------------------------------------------------
__device__ __align__(256) bf16 g_xn_hi[MTOT*DIMX];
__device__ __align__(256) bf16 g_xn_lo[MTOT*DIMX];
__device__ __align__(256) half g_qf  [MTOT*DIMX];          // fp16 Q
__device__ __align__(256) bf16 g_ao_hi[MTOT*DIMX];
__device__ __align__(256) bf16 g_ao_lo[MTOT*DIMX];
__device__ __align__(256) float g_o2  [MTOT*DIMX];
__device__ __align__(256) half g_kf  [BB*NKPAD*DHD];       // fp16 K
__device__ __align__(256) half g_vtf [BB*DHD*NKPAD];       // fp16 V^T
__device__ __align__(256) bf16 g_wq_hi[DIMX*DIMX];
__device__ __align__(256) bf16 g_wq_lo[DIMX*DIMX];
__device__ __align__(256) bf16 g_wk_hi[128*DIMX];
__device__ __align__(256) bf16 g_wk_lo[128*DIMX];
__device__ __align__(256) bf16 g_wo_hi[DIMX*DIMX];
__device__ __align__(256) bf16 g_wo_lo[DIMX*DIMX];
__device__ __align__(256) float g_mskf[BB*NKPAD];

// ---------------- helpers --------------------------------------------------
__device__ __forceinline__ uint32_t smem_u32(const void* p) {
    uint32_t a;
    asm("{ .reg .u64 t; cvta.to.shared.u64 t, %1; cvt.u32.u64 %0, t; }" : "=r"(a) : "l"(p));
    return a;
}
__device__ __forceinline__ void ldsm4(uint32_t (&r)[4], uint32_t a) {
    asm volatile("ldmatrix.sync.aligned.m8n8.x4.shared.b16 {%0,%1,%2,%3}, [%4];"
                 : "=r"(r[0]), "=r"(r[1]), "=r"(r[2]), "=r"(r[3]) : "r"(a));
}
__device__ __forceinline__ void ldsm2(uint32_t (&r)[2], uint32_t a) {
    asm volatile("ldmatrix.sync.aligned.m8n8.x2.shared.b16 {%0,%1}, [%2];"
                 : "=r"(r[0]), "=r"(r[1]) : "r"(a));
}
__device__ __forceinline__ void mma_bf(float (&d)[4], const uint32_t (&a)[4], const uint32_t (&b)[2]) {
    asm volatile("mma.sync.aligned.m16n8k16.row.col.f32.bf16.bf16.f32 "
                 "{%0,%1,%2,%3}, {%4,%5,%6,%7}, {%8,%9}, {%0,%1,%2,%3};"
                 : "+f"(d[0]), "+f"(d[1]), "+f"(d[2]), "+f"(d[3])
                 : "r"(a[0]), "r"(a[1]), "r"(a[2]), "r"(a[3]), "r"(b[0]), "r"(b[1]));
}
__device__ __forceinline__ void mma_f16(float (&d)[4], const uint32_t (&a)[4], const uint32_t (&b)[2]) {
    asm volatile("mma.sync.aligned.m16n8k16.row.col.f32.f16.f16.f32 "
                 "{%0,%1,%2,%3}, {%4,%5,%6,%7}, {%8,%9}, {%0,%1,%2,%3};"
                 : "+f"(d[0]), "+f"(d[1]), "+f"(d[2]), "+f"(d[3])
                 : "r"(a[0]), "r"(a[1]), "r"(a[2]), "r"(a[3]), "r"(b[0]), "r"(b[1]));
}
#define CP16(dst, src) asm volatile("cp.async.cg.shared.global [%0], [%1], 16;" :: "r"(dst), "l"(src) : "memory")
#define CP4(dst, src)  asm volatile("cp.async.ca.shared.global [%0], [%1], 4;"  :: "r"(dst), "l"(src) : "memory")
#define CP_COMMIT()    asm volatile("cp.async.commit_group;" ::: "memory")
#define CP_WAIT0()     asm volatile("cp.async.wait_group 0;" ::: "memory")
#define CP_WAIT1()     asm volatile("cp.async.wait_group 1;" ::: "memory")

__device__ __forceinline__ void split2(float v, bf16& h, bf16& l) {
    h = __float2bfloat16(v);
    l = __float2bfloat16(v - __bfloat162float(h));
}
__device__ __forceinline__ uint32_t packh2(float a, float b) {   // a -> low half
    uint32_t r;
    asm("cvt.rn.f16x2.f32 %0, %2, %1;" : "=r"(r) : "f"(a), "f"(b));
    return r;
}
__device__ __forceinline__ void splitpack(float a, float b, uint32_t& hw, uint32_t& lw) {
    asm("cvt.rn.bf16x2.f32 %0, %2, %1;" : "=r"(hw) : "f"(a), "f"(b));
    float ha = __uint_as_float(hw << 16);
    float hb = __uint_as_float(hw & 0xFFFF0000u);
    float la = a - ha, lb = b - hb;
    asm("cvt.rn.bf16x2.f32 %0, %2, %1;" : "=r"(lw) : "f"(la), "f"(lb));
}

// ---------------- LayerNorm (SPLIT=1: bf16 hi/lo; 0: fp32) ----------------
template<int SPLIT>
__global__ __launch_bounds__(128) void ln_k(const float* __restrict__ x, const float* __restrict__ g,
                                            float* __restrict__ yf, bf16* __restrict__ yh, bf16* __restrict__ yl) {
    int row = blockIdx.x, t = threadIdx.x;
    float4 v = reinterpret_cast<const float4*>(x + (size_t)row*DIMX)[t];
    float s  = v.x + v.y + v.z + v.w;
    float s2 = v.x*v.x + v.y*v.y + v.z*v.z + v.w*v.w;
#pragma unroll
    for (int o = 16; o > 0; o >>= 1) {
        s  += __shfl_xor_sync(0xffffffffu, s,  o);
        s2 += __shfl_xor_sync(0xffffffffu, s2, o);
    }
    __shared__ float ws[4], ws2[4];
    int w = t >> 5;
    if ((t & 31) == 0) { ws[w] = s; ws2[w] = s2; }
    __syncthreads();
    float S = ws[0]+ws[1]+ws[2]+ws[3], S2 = ws2[0]+ws2[1]+ws2[2]+ws2[3];
    float mu = S * (1.0f/DIMX);
    float r = rsqrtf(S2*(1.0f/DIMX) - mu*mu + 1e-5f);
    float4 gg = reinterpret_cast<const float4*>(g)[t];
    float o0=(v.x-mu)*r*gg.x, o1=(v.y-mu)*r*gg.y, o2=(v.z-mu)*r*gg.z, o3=(v.w-mu)*r*gg.w;
    if (SPLIT == 0) {
        reinterpret_cast<float4*>(yf + (size_t)row*DIMX)[t] = make_float4(o0,o1,o2,o3);
    } else {
        uint2 hw, lw;
        splitpack(o0, o1, hw.x, lw.x);
        splitpack(o2, o3, hw.y, lw.y);
        *reinterpret_cast<uint2*>(yh + (size_t)row*DIMX + t*4) = hw;
        *reinterpret_cast<uint2*>(yl + (size_t)row*DIMX + t*4) = lw;
    }
}

// ---------------- weight transpose + split: W[k][N] -> hi/lo[n][k] ---------
__global__ void tsplit_k(const float* __restrict__ W, bf16* __restrict__ hi, bf16* __restrict__ lo, int N) {
    __shared__ float t[32][33];
    int n0 = blockIdx.x*32, k0 = blockIdx.y*32;
    int tx = threadIdx.x, ty = threadIdx.y;
    for (int r = ty; r < 32; r += 8) t[r][tx] = W[(size_t)(k0+r)*N + n0+tx];
    __syncthreads();
    for (int r = ty; r < 32; r += 8) {
        bf16 h, l; split2(t[tx][r], h, l);
        hi[(size_t)(n0+r)*DIMX + k0+tx] = h;
        lo[(size_t)(n0+r)*DIMX + k0+tx] = l;
    }
}

// ---------------- null kv + key padding + mask floats ----------------------
__global__ void kvinit_k(const float* __restrict__ nkv, const unsigned* __restrict__ mask) {
    int e = blockIdx.x*256 + threadIdx.x;
    if (e < 256) {
        int b = e >> 6, d = e & 63;
        g_kf [(size_t)b*NKPAD*DHD + d]      = __float2half(nkv[d]);
        g_vtf[((size_t)b*DHD+d)*NKPAD]      = __float2half(nkv[64+d]);
    }
    if (e < BB*255*DHD) {
        int b = e/(255*DHD), rem = e%(255*DHD);
        int key = 2049 + rem/DHD, d = rem % DHD;
        g_kf [((size_t)b*NKPAD+key)*DHD + d]   = __float2half(0.f);
        g_vtf[((size_t)b*DHD+d)*NKPAD + key]   = __float2half(0.f);
    }
    if (e < BB*NKPAD) {
        int b = e / NKPAD, jj = e % NKPAD;
        float v;
        if (jj == 0)         v = 1.f;
        else if (jj < NKEY)  v = (mask[(size_t)b*NN + jj - 1] != 0u) ? 1.f : 0.f;
        else                 v = 0.f;
        g_mskf[e] = v;
    }
}

// ---------------- mma.sync split-precision GEMM ----------------------------
#define LDA 40
template<int MODE>
__global__ __launch_bounds__(256,2) void gemm_mma(const bf16* __restrict__ Ah, const bf16* __restrict__ Al,
                                                  const bf16* __restrict__ Bh, const bf16* __restrict__ Bl,
                                                  float* __restrict__ C) {
    __shared__ bf16 At[128*LDA];
    __shared__ bf16 Bt[128*LDA];
    int tid = threadIdx.x, wid = tid >> 5, lane = tid & 31;
    int m0 = blockIdx.y*128, n0 = blockIdx.x*128;
    int wm = (wid & 3)*32, wn = (wid >> 2)*64;
    uint32_t sA = smem_u32(At), sB = smem_u32(Bt);
    int ldr = tid >> 1, ldc = (tid & 1)*16;
    int r16 = lane & 15, c8 = (lane >> 4) << 3, tt = lane & 15;

    float acc[2][8][4];
#pragma unroll
    for (int i = 0; i < 2; i++)
#pragma unroll
        for (int n = 0; n < 8; n++)
#pragma unroll
            for (int j = 0; j < 4; j++) acc[i][n][j] = 0.f;

    for (int term = 0; term < 3; term++) {
        const bf16* Ap = (term == 1) ? Al : Ah;
        const bf16* Bp = (term == 2) ? Bl : Bh;
        for (int k0 = 0; k0 < DIMX; k0 += 32) {
            __syncthreads();
            const uint4* ag = reinterpret_cast<const uint4*>(Ap + (size_t)(m0+ldr)*DIMX + k0 + ldc);
            const uint4* bg = reinterpret_cast<const uint4*>(Bp + (size_t)(n0+ldr)*DIMX + k0 + ldc);
            uint4 a0 = ag[0], a1 = ag[1], b0 = bg[0], b1 = bg[1];
            *reinterpret_cast<uint4*>((char*)At + ldr*80 + ldc*2)      = a0;
            *reinterpret_cast<uint4*>((char*)At + ldr*80 + ldc*2 + 16) = a1;
            *reinterpret_cast<uint4*>((char*)Bt + ldr*80 + ldc*2)      = b0;
            *reinterpret_cast<uint4*>((char*)Bt + ldr*80 + ldc*2 + 16) = b1;
            __syncthreads();
#pragma unroll
            for (int kk = 0; kk < 32; kk += 16) {
                uint32_t af0[4], af1[4];
                ldsm4(af0, sA + (uint32_t)((wm      + r16)*80 + (kk + c8)*2));
                ldsm4(af1, sA + (uint32_t)((wm + 16 + r16)*80 + (kk + c8)*2));
#pragma unroll
                for (int nf = 0; nf < 8; nf++) {
                    uint32_t bb[2];
                    ldsm2(bb, sB + (uint32_t)((wn + nf*8 + (tt & 7))*80 + (kk + ((tt >> 3) << 3))*2));
                    mma_bf(acc[0][nf], af0, bb);
                    mma_bf(acc[1][nf], af1, bb);
                }
            }
        }
    }

    int r4 = lane >> 2, c2 = (lane & 3)*2;
#pragma unroll
    for (int mf = 0; mf < 2; mf++) {
        int mA = m0 + wm + mf*16 + r4, mB = mA + 8;
#pragma unroll
        for (int nf = 0; nf < 8; nf++) {
            int nc = n0 + wn + nf*8 + c2;
            float v0 = acc[mf][nf][0], v1 = acc[mf][nf][1];
            float v2 = acc[mf][nf][2], v3 = acc[mf][nf][3];
            if (MODE == 0) {
                *reinterpret_cast<float2*>(C + (size_t)mA*DIMX + nc) = make_float2(v0, v1);
                *reinterpret_cast<float2*>(C + (size_t)mB*DIMX + nc) = make_float2(v2, v3);
            } else if (MODE == 1) {
                *reinterpret_cast<uint32_t*>(g_qf + (size_t)mA*DIMX + nc) = packh2(v0*0.125f, v1*0.125f);
                *reinterpret_cast<uint32_t*>(g_qf + (size_t)mB*DIMX + nc) = packh2(v2*0.125f, v3*0.125f);
            } else {
                int bA = mA >> 11, keyA = 1 + (mA & 2047);
                int bB = mB >> 11, keyB = 1 + (mB & 2047);
                if (nc < DHD) {
                    *reinterpret_cast<uint32_t*>(g_kf + ((size_t)bA*NKPAD+keyA)*DHD + nc) = packh2(v0, v1);
                    *reinterpret_cast<uint32_t*>(g_kf + ((size_t)bB*NKPAD+keyB)*DHD + nc) = packh2(v2, v3);
                } else {
                    int d = nc - DHD;
                    g_vtf[((size_t)bA*DHD+d  )*NKPAD + keyA] = __float2half(v0);
                    g_vtf[((size_t)bA*DHD+d+1)*NKPAD + keyA] = __float2half(v1);
                    g_vtf[((size_t)bB*DHD+d  )*NKPAD + keyB] = __float2half(v2);
                    g_vtf[((size_t)bB*DHD+d+1)*NKPAD + keyB] = __float2half(v3);
                }
            }
        }
    }
}

// ---------------- attention: fp16 single-term S and PV ---------------------
// stage: Kf [128][144B] @0 (18432), VTf [64][272B] @18432 (17408),
// mask @35840 (512). STG=36352; double-buffered = 72704 B.
#define STG 36352u
#define ATTN_SMEM (2*STG)

__device__ __forceinline__ void attn_issue(uint32_t dstbase, int b, int t0, int tid) {
#pragma unroll
    for (int rep = 0; rep < 4; rep++) {                    // Kf: 128 rows x 128B
        int idx = rep*256 + tid;
        int row = idx >> 3, ch = idx & 7;
        const half* src = g_kf + ((size_t)b*NKPAD + t0*128 + row)*DHD + ch*8;
        CP16(dstbase + (uint32_t)(row*144 + ch*16), src);
    }
#pragma unroll
    for (int rep = 0; rep < 4; rep++) {                    // VTf: 64 rows x 256B
        int idx = rep*256 + tid;
        int row = idx >> 4, ch = idx & 15;
        const half* src = g_vtf + ((size_t)b*DHD + row)*NKPAD + t0*128 + ch*8;
        CP16(dstbase + 18432u + (uint32_t)(row*272 + ch*16), src);
    }
    if (tid < 128) {
        const float* src = g_mskf + (size_t)b*NKPAD + t0*128 + tid;
        CP4(dstbase + 35840u + (uint32_t)(tid*4), src);
    }
    CP_COMMIT();
}

__global__ __launch_bounds__(256,1) void attn_mma(const unsigned* __restrict__ mask) {
    extern __shared__ __align__(128) char sm[];
    uint32_t sb = smem_u32(sm);
    int tid = threadIdx.x, wid = tid >> 5, lane = tid & 31;
    int m0 = blockIdx.x*128, h = blockIdx.y, b = blockIdx.z;
    int r16 = lane & 15, c8 = (lane >> 4) << 3, tt = lane & 15;

    // ---- stage Q (fp16) into stage-0 Kf region, pull frags to regs ----
#pragma unroll
    for (int rep = 0; rep < 4; rep++) {
        int idx = rep*256 + tid;
        int row = idx >> 3, ch = idx & 7;
        const half* src = g_qf + ((size_t)(b*NN + m0 + row))*DIMX + h*DHD + ch*8;
        *reinterpret_cast<uint4*>(sm + row*144 + ch*16) = *reinterpret_cast<const uint4*>(src);
    }
    __syncthreads();
    uint32_t qf[4][4];
#pragma unroll
    for (int k = 0; k < 4; k++)
        ldsm4(qf[k], sb + (uint32_t)((wid*16 + r16)*144 + (k*16 + c8)*2));
    __syncthreads();

    float o[8][4];
#pragma unroll
    for (int n = 0; n < 8; n++)
#pragma unroll
        for (int j = 0; j < 4; j++) o[n][j] = 0.f;
    float lsum0 = 0.f, lsum1 = 0.f;

    attn_issue(sb, b, 0, tid);

    for (int t0 = 0; t0 < NKPAD/128; t0++) {
        uint32_t stb = sb + (uint32_t)(t0 & 1)*STG;
        if (t0 < NKPAD/128 - 1) {
            attn_issue(sb + (uint32_t)((t0+1) & 1)*STG, b, t0+1, tid);
            CP_WAIT1();
        } else {
            CP_WAIT0();
        }
        __syncthreads();
        const float* msk = reinterpret_cast<const float*>(sm + (t0 & 1)*STG + 35840);

        // ---- S = Q K^T, single fp16 term ----
        float s[16][4];
#pragma unroll
        for (int n = 0; n < 16; n++)
#pragma unroll
            for (int j = 0; j < 4; j++) s[n][j] = 0.f;
#pragma unroll
        for (int k = 0; k < 4; k++) {
#pragma unroll
            for (int nf = 0; nf < 16; nf++) {
                uint32_t kb[2];
                ldsm2(kb, stb + (uint32_t)((nf*8 + (tt & 7))*144 + (k*16 + ((tt >> 3) << 3))*2));
                mma_f16(s[nf], qf[k], kb);
            }
        }

        // ---- softmax (MUFU exp; no max subtraction) ----
#pragma unroll
        for (int nf = 0; nf < 16; nf++) {
            int colb = nf*8 + 2*(lane & 3);
            float m0f = msk[colb], m1f = msk[colb + 1];
            float p0 = __expf(s[nf][0]) * m0f;
            float p1 = __expf(s[nf][1]) * m1f;
            float p2 = __expf(s[nf][2]) * m0f;
            float p3 = __expf(s[nf][3]) * m1f;
            s[nf][0] = p0; s[nf][1] = p1; s[nf][2] = p2; s[nf][3] = p3;
            lsum0 += p0 + p1; lsum1 += p2 + p3;
        }

        // ---- O += P V, single fp16 term ----
#pragma unroll
        for (int kt = 0; kt < 8; kt++) {
            uint32_t ph[4];
            ph[0] = packh2(s[2*kt  ][0], s[2*kt  ][1]);
            ph[1] = packh2(s[2*kt  ][2], s[2*kt  ][3]);
            ph[2] = packh2(s[2*kt+1][0], s[2*kt+1][1]);
            ph[3] = packh2(s[2*kt+1][2], s[2*kt+1][3]);
#pragma unroll
            for (int nf = 0; nf < 8; nf++) {
                uint32_t vf[2];
                ldsm2(vf, stb + 18432 + (uint32_t)((nf*8 + (tt & 7))*272 + (kt*16 + ((tt >> 3) << 3))*2));
                mma_f16(o[nf], ph, vf);
            }
        }
        __syncthreads();
    }

    // ---- finalize ----
    lsum0 += __shfl_xor_sync(0xffffffffu, lsum0, 1);
    lsum0 += __shfl_xor_sync(0xffffffffu, lsum0, 2);
    lsum1 += __shfl_xor_sync(0xffffffffu, lsum1, 1);
    lsum1 += __shfl_xor_sync(0xffffffffu, lsum1, 2);
    float inv0 = 1.f / lsum0, inv1 = 1.f / lsum1;
    size_t rowA = (size_t)(b*NN + m0 + wid*16 + (lane >> 2));
    size_t rowB = rowA + 8;
    int colb = h*DHD + 2*(lane & 3);
#pragma unroll
    for (int nf = 0; nf < 8; nf++) {
        int nc = colb + nf*8;
        uint32_t hw, lw;
        splitpack(o[nf][0]*inv0, o[nf][1]*inv0, hw, lw);
        *reinterpret_cast<uint32_t*>(g_ao_hi + rowA*DIMX + nc) = hw;
        *reinterpret_cast<uint32_t*>(g_ao_lo + rowA*DIMX + nc) = lw;
        splitpack(o[nf][2]*inv1, o[nf][3]*inv1, hw, lw);
        *reinterpret_cast<uint32_t*>(g_ao_hi + rowB*DIMX + nc) = hw;
        *reinterpret_cast<uint32_t*>(g_ao_lo + rowB*DIMX + nc) = lw;
    }
}

// ---------------- launch ----------------------------------------------------
extern "C" void kernel_launch(void* const* d_in, const int* in_sizes, int n_in,
                              void* d_out, int out_size) {
    const float*    x      = (const float*)d_in[0];
    const unsigned* mask   = (const unsigned*)d_in[1];
    const float*    gamma  = (const float*)d_in[2];
    const float*    Wq     = (const float*)d_in[3];
    const float*    Wkv    = (const float*)d_in[4];
    const float*    nkv    = (const float*)d_in[5];
    const float*    Wout   = (const float*)d_in[6];
    const float*    ogamma = (const float*)d_in[7];
    float*          out    = (float*)d_out;

    float *o2;
    bf16 *xnh, *xnl, *wqh, *wql, *wkh, *wkl, *woh, *wol, *aoh, *aol;
    cudaGetSymbolAddress((void**)&o2,  g_o2);
    cudaGetSymbolAddress((void**)&xnh, g_xn_hi); cudaGetSymbolAddress((void**)&xnl, g_xn_lo);
    cudaGetSymbolAddress((void**)&wqh, g_wq_hi); cudaGetSymbolAddress((void**)&wql, g_wq_lo);
    cudaGetSymbolAddress((void**)&wkh, g_wk_hi); cudaGetSymbolAddress((void**)&wkl, g_wk_lo);
    cudaGetSymbolAddress((void**)&woh, g_wo_hi); cudaGetSymbolAddress((void**)&wol, g_wo_lo);
    cudaGetSymbolAddress((void**)&aoh, g_ao_hi); cudaGetSymbolAddress((void**)&aol, g_ao_lo);
    cudaFuncSetAttribute(attn_mma, cudaFuncAttributeMaxDynamicSharedMemorySize, ATTN_SMEM);

    ln_k<1><<<MTOT, 128>>>(x, gamma, nullptr, xnh, xnl);
    tsplit_k<<<dim3(16,16), dim3(32,8)>>>(Wq,   wqh, wql, 512);
    tsplit_k<<<dim3(4, 16), dim3(32,8)>>>(Wkv,  wkh, wkl, 128);
    tsplit_k<<<dim3(16,16), dim3(32,8)>>>(Wout, woh, wol, 512);
    kvinit_k<<<255, 256>>>(nkv, mask);
    gemm_mma<1><<<dim3(4,64), 256>>>(xnh, xnl, wqh, wql, nullptr);
    gemm_mma<2><<<dim3(1,64), 256>>>(xnh, xnl, wkh, wkl, nullptr);
    attn_mma<<<dim3(16,8,4), 256, ATTN_SMEM>>>(mask);
    gemm_mma<0><<<dim3(4,64), 256>>>(aoh, aol, woh, wol, o2);
    ln_k<0><<<MTOT, 128>>>(o2, ogamma, out, nullptr, nullptr);
}

// round 17
// speedup vs baseline: 2.4071x; 1.0058x over previous
#include <cuda_runtime.h>
#include <cuda_bf16.h>
#include <cuda_fp16.h>
#include <cstdint>

#define BB 4
#define NN 2048
#define DIMX 512
#define DHD 64
#define NKEY 2049
#define NKPAD 2304
#define MTOT (BB*NN)
typedef __nv_bfloat16 bf16;

// ---------------- scratch --------------------------------------------------
__device__ __align__(256) bf16 g_xn_hi[MTOT*DIMX];
__device__ __align__(256) bf16 g_xn_lo[MTOT*DIMX];
__device__ __align__(256) half g_qf  [MTOT*DIMX];          // fp16 Q
__device__ __align__(256) bf16 g_ao_hi[MTOT*DIMX];
__device__ __align__(256) bf16 g_ao_lo[MTOT*DIMX];
__device__ __align__(256) float g_o2  [MTOT*DIMX];
__device__ __align__(256) half g_kf  [BB*NKPAD*DHD];       // fp16 K
__device__ __align__(256) half g_vtf [BB*DHD*NKPAD];       // fp16 V^T
__device__ __align__(256) bf16 g_wq_hi[DIMX*DIMX];
__device__ __align__(256) bf16 g_wq_lo[DIMX*DIMX];
__device__ __align__(256) bf16 g_wk_hi[128*DIMX];
__device__ __align__(256) bf16 g_wk_lo[128*DIMX];
__device__ __align__(256) bf16 g_wo_hi[DIMX*DIMX];
__device__ __align__(256) bf16 g_wo_lo[DIMX*DIMX];
__device__ __align__(256) float g_mskf[BB*NKPAD];

// ---------------- helpers --------------------------------------------------
__device__ __forceinline__ uint32_t smem_u32(const void* p) {
    uint32_t a;
    asm("{ .reg .u64 t; cvta.to.shared.u64 t, %1; cvt.u32.u64 %0, t; }" : "=r"(a) : "l"(p));
    return a;
}
__device__ __forceinline__ void ldsm4(uint32_t (&r)[4], uint32_t a) {
    asm volatile("ldmatrix.sync.aligned.m8n8.x4.shared.b16 {%0,%1,%2,%3}, [%4];"
                 : "=r"(r[0]), "=r"(r[1]), "=r"(r[2]), "=r"(r[3]) : "r"(a));
}
__device__ __forceinline__ void ldsm2(uint32_t (&r)[2], uint32_t a) {
    asm volatile("ldmatrix.sync.aligned.m8n8.x2.shared.b16 {%0,%1}, [%2];"
                 : "=r"(r[0]), "=r"(r[1]) : "r"(a));
}
__device__ __forceinline__ void mma_bf(float (&d)[4], const uint32_t (&a)[4], const uint32_t (&b)[2]) {
    asm volatile("mma.sync.aligned.m16n8k16.row.col.f32.bf16.bf16.f32 "
                 "{%0,%1,%2,%3}, {%4,%5,%6,%7}, {%8,%9}, {%0,%1,%2,%3};"
                 : "+f"(d[0]), "+f"(d[1]), "+f"(d[2]), "+f"(d[3])
                 : "r"(a[0]), "r"(a[1]), "r"(a[2]), "r"(a[3]), "r"(b[0]), "r"(b[1]));
}
__device__ __forceinline__ void mma_f16(float (&d)[4], const uint32_t (&a)[4], const uint32_t (&b)[2]) {
    asm volatile("mma.sync.aligned.m16n8k16.row.col.f32.f16.f16.f32 "
                 "{%0,%1,%2,%3}, {%4,%5,%6,%7}, {%8,%9}, {%0,%1,%2,%3};"
                 : "+f"(d[0]), "+f"(d[1]), "+f"(d[2]), "+f"(d[3])
                 : "r"(a[0]), "r"(a[1]), "r"(a[2]), "r"(a[3]), "r"(b[0]), "r"(b[1]));
}
#define CP16(dst, src) asm volatile("cp.async.cg.shared.global [%0], [%1], 16;" :: "r"(dst), "l"(src) : "memory")
#define CP4(dst, src)  asm volatile("cp.async.ca.shared.global [%0], [%1], 4;"  :: "r"(dst), "l"(src) : "memory")
#define CP_COMMIT()    asm volatile("cp.async.commit_group;" ::: "memory")
#define CP_WAIT0()     asm volatile("cp.async.wait_group 0;" ::: "memory")
#define CP_WAIT1()     asm volatile("cp.async.wait_group 1;" ::: "memory")

__device__ __forceinline__ void split2(float v, bf16& h, bf16& l) {
    h = __float2bfloat16(v);
    l = __float2bfloat16(v - __bfloat162float(h));
}
__device__ __forceinline__ uint32_t packh2(float a, float b) {   // a -> low half
    uint32_t r;
    asm("cvt.rn.f16x2.f32 %0, %2, %1;" : "=r"(r) : "f"(a), "f"(b));
    return r;
}
__device__ __forceinline__ void splitpack(float a, float b, uint32_t& hw, uint32_t& lw) {
    asm("cvt.rn.bf16x2.f32 %0, %2, %1;" : "=r"(hw) : "f"(a), "f"(b));
    float ha = __uint_as_float(hw << 16);
    float hb = __uint_as_float(hw & 0xFFFF0000u);
    float la = a - ha, lb = b - hb;
    asm("cvt.rn.bf16x2.f32 %0, %2, %1;" : "=r"(lw) : "f"(la), "f"(lb));
}

// ---------------- LayerNorm (SPLIT=1: bf16 hi/lo; 0: fp32) ----------------
template<int SPLIT>
__global__ __launch_bounds__(128) void ln_k(const float* __restrict__ x, const float* __restrict__ g,
                                            float* __restrict__ yf, bf16* __restrict__ yh, bf16* __restrict__ yl) {
    int row = blockIdx.x, t = threadIdx.x;
    float4 v = reinterpret_cast<const float4*>(x + (size_t)row*DIMX)[t];
    float s  = v.x + v.y + v.z + v.w;
    float s2 = v.x*v.x + v.y*v.y + v.z*v.z + v.w*v.w;
#pragma unroll
    for (int o = 16; o > 0; o >>= 1) {
        s  += __shfl_xor_sync(0xffffffffu, s,  o);
        s2 += __shfl_xor_sync(0xffffffffu, s2, o);
    }
    __shared__ float ws[4], ws2[4];
    int w = t >> 5;
    if ((t & 31) == 0) { ws[w] = s; ws2[w] = s2; }
    __syncthreads();
    float S = ws[0]+ws[1]+ws[2]+ws[3], S2 = ws2[0]+ws2[1]+ws2[2]+ws2[3];
    float mu = S * (1.0f/DIMX);
    float r = rsqrtf(S2*(1.0f/DIMX) - mu*mu + 1e-5f);
    float4 gg = reinterpret_cast<const float4*>(g)[t];
    float o0=(v.x-mu)*r*gg.x, o1=(v.y-mu)*r*gg.y, o2=(v.z-mu)*r*gg.z, o3=(v.w-mu)*r*gg.w;
    if (SPLIT == 0) {
        reinterpret_cast<float4*>(yf + (size_t)row*DIMX)[t] = make_float4(o0,o1,o2,o3);
    } else {
        uint2 hw, lw;
        splitpack(o0, o1, hw.x, lw.x);
        splitpack(o2, o3, hw.y, lw.y);
        *reinterpret_cast<uint2*>(yh + (size_t)row*DIMX + t*4) = hw;
        *reinterpret_cast<uint2*>(yl + (size_t)row*DIMX + t*4) = lw;
    }
}

// ---------------- weight transpose + split: W[k][N] -> hi/lo[n][k] ---------
__global__ void tsplit_k(const float* __restrict__ W, bf16* __restrict__ hi, bf16* __restrict__ lo, int N) {
    __shared__ float t[32][33];
    int n0 = blockIdx.x*32, k0 = blockIdx.y*32;
    int tx = threadIdx.x, ty = threadIdx.y;
    for (int r = ty; r < 32; r += 8) t[r][tx] = W[(size_t)(k0+r)*N + n0+tx];
    __syncthreads();
    for (int r = ty; r < 32; r += 8) {
        bf16 h, l; split2(t[tx][r], h, l);
        hi[(size_t)(n0+r)*DIMX + k0+tx] = h;
        lo[(size_t)(n0+r)*DIMX + k0+tx] = l;
    }
}

// ---------------- null kv + key padding + mask floats ----------------------
__global__ void kvinit_k(const float* __restrict__ nkv, const unsigned* __restrict__ mask) {
    int e = blockIdx.x*256 + threadIdx.x;
    if (e < 256) {
        int b = e >> 6, d = e & 63;
        g_kf [(size_t)b*NKPAD*DHD + d]      = __float2half(nkv[d]);
        g_vtf[((size_t)b*DHD+d)*NKPAD]      = __float2half(nkv[64+d]);
    }
    if (e < BB*255*DHD) {
        int b = e/(255*DHD), rem = e%(255*DHD);
        int key = 2049 + rem/DHD, d = rem % DHD;
        g_kf [((size_t)b*NKPAD+key)*DHD + d]   = __float2half(0.f);
        g_vtf[((size_t)b*DHD+d)*NKPAD + key]   = __float2half(0.f);
    }
    if (e < BB*NKPAD) {
        int b = e / NKPAD, jj = e % NKPAD;
        float v;
        if (jj == 0)         v = 1.f;
        else if (jj < NKEY)  v = (mask[(size_t)b*NN + jj - 1] != 0u) ? 1.f : 0.f;
        else                 v = 0.f;
        g_mskf[e] = v;
    }
}

// ---------------- mma.sync split-precision GEMM ----------------------------
#define LDA 40
template<int MODE>
__global__ __launch_bounds__(256,2) void gemm_mma(const bf16* __restrict__ Ah, const bf16* __restrict__ Al,
                                                  const bf16* __restrict__ Bh, const bf16* __restrict__ Bl,
                                                  float* __restrict__ C) {
    __shared__ bf16 At[128*LDA];
    __shared__ bf16 Bt[128*LDA];
    int tid = threadIdx.x, wid = tid >> 5, lane = tid & 31;
    int m0 = blockIdx.y*128, n0 = blockIdx.x*128;
    int wm = (wid & 3)*32, wn = (wid >> 2)*64;
    uint32_t sA = smem_u32(At), sB = smem_u32(Bt);
    int ldr = tid >> 1, ldc = (tid & 1)*16;
    int r16 = lane & 15, c8 = (lane >> 4) << 3, tt = lane & 15;

    float acc[2][8][4];
#pragma unroll
    for (int i = 0; i < 2; i++)
#pragma unroll
        for (int n = 0; n < 8; n++)
#pragma unroll
            for (int j = 0; j < 4; j++) acc[i][n][j] = 0.f;

    for (int term = 0; term < 3; term++) {
        const bf16* Ap = (term == 1) ? Al : Ah;
        const bf16* Bp = (term == 2) ? Bl : Bh;
        for (int k0 = 0; k0 < DIMX; k0 += 32) {
            __syncthreads();
            const uint4* ag = reinterpret_cast<const uint4*>(Ap + (size_t)(m0+ldr)*DIMX + k0 + ldc);
            const uint4* bg = reinterpret_cast<const uint4*>(Bp + (size_t)(n0+ldr)*DIMX + k0 + ldc);
            uint4 a0 = ag[0], a1 = ag[1], b0 = bg[0], b1 = bg[1];
            *reinterpret_cast<uint4*>((char*)At + ldr*80 + ldc*2)      = a0;
            *reinterpret_cast<uint4*>((char*)At + ldr*80 + ldc*2 + 16) = a1;
            *reinterpret_cast<uint4*>((char*)Bt + ldr*80 + ldc*2)      = b0;
            *reinterpret_cast<uint4*>((char*)Bt + ldr*80 + ldc*2 + 16) = b1;
            __syncthreads();
#pragma unroll
            for (int kk = 0; kk < 32; kk += 16) {
                uint32_t af0[4], af1[4];
                ldsm4(af0, sA + (uint32_t)((wm      + r16)*80 + (kk + c8)*2));
                ldsm4(af1, sA + (uint32_t)((wm + 16 + r16)*80 + (kk + c8)*2));
#pragma unroll
                for (int nf = 0; nf < 8; nf++) {
                    uint32_t bb[2];
                    ldsm2(bb, sB + (uint32_t)((wn + nf*8 + (tt & 7))*80 + (kk + ((tt >> 3) << 3))*2));
                    mma_bf(acc[0][nf], af0, bb);
                    mma_bf(acc[1][nf], af1, bb);
                }
            }
        }
    }

    int r4 = lane >> 2, c2 = (lane & 3)*2;
#pragma unroll
    for (int mf = 0; mf < 2; mf++) {
        int mA = m0 + wm + mf*16 + r4, mB = mA + 8;
#pragma unroll
        for (int nf = 0; nf < 8; nf++) {
            int nc = n0 + wn + nf*8 + c2;
            float v0 = acc[mf][nf][0], v1 = acc[mf][nf][1];
            float v2 = acc[mf][nf][2], v3 = acc[mf][nf][3];
            if (MODE == 0) {
                *reinterpret_cast<float2*>(C + (size_t)mA*DIMX + nc) = make_float2(v0, v1);
                *reinterpret_cast<float2*>(C + (size_t)mB*DIMX + nc) = make_float2(v2, v3);
            } else if (MODE == 1) {
                *reinterpret_cast<uint32_t*>(g_qf + (size_t)mA*DIMX + nc) = packh2(v0*0.125f, v1*0.125f);
                *reinterpret_cast<uint32_t*>(g_qf + (size_t)mB*DIMX + nc) = packh2(v2*0.125f, v3*0.125f);
            } else {
                int bA = mA >> 11, keyA = 1 + (mA & 2047);
                int bB = mB >> 11, keyB = 1 + (mB & 2047);
                if (nc < DHD) {
                    *reinterpret_cast<uint32_t*>(g_kf + ((size_t)bA*NKPAD+keyA)*DHD + nc) = packh2(v0, v1);
                    *reinterpret_cast<uint32_t*>(g_kf + ((size_t)bB*NKPAD+keyB)*DHD + nc) = packh2(v2, v3);
                } else {
                    int d = nc - DHD;
                    g_vtf[((size_t)bA*DHD+d  )*NKPAD + keyA] = __float2half(v0);
                    g_vtf[((size_t)bA*DHD+d+1)*NKPAD + keyA] = __float2half(v1);
                    g_vtf[((size_t)bB*DHD+d  )*NKPAD + keyB] = __float2half(v2);
                    g_vtf[((size_t)bB*DHD+d+1)*NKPAD + keyB] = __float2half(v3);
                }
            }
        }
    }
}

// ---------------- attention: fp16 S and PV, half-tile phases, 2 CTAs/SM ----
// stage: Kf [128][144B] @0 (18432), VTf [64][272B] @18432 (17408),
// mask @35840 (512). STG=36352; double-buffered = 72704 B. 2 CTAs/SM.
#define STG 36352u
#define ATTN_SMEM (2*STG)

__device__ __forceinline__ void attn_issue(uint32_t dstbase, int b, int t0, int tid) {
#pragma unroll
    for (int rep = 0; rep < 4; rep++) {                    // Kf: 128 rows x 128B
        int idx = rep*256 + tid;
        int row = idx >> 3, ch = idx & 7;
        const half* src = g_kf + ((size_t)b*NKPAD + t0*128 + row)*DHD + ch*8;
        CP16(dstbase + (uint32_t)(row*144 + ch*16), src);
    }
#pragma unroll
    for (int rep = 0; rep < 4; rep++) {                    // VTf: 64 rows x 256B
        int idx = rep*256 + tid;
        int row = idx >> 4, ch = idx & 15;
        const half* src = g_vtf + ((size_t)b*DHD + row)*NKPAD + t0*128 + ch*8;
        CP16(dstbase + 18432u + (uint32_t)(row*272 + ch*16), src);
    }
    if (tid < 128) {
        const float* src = g_mskf + (size_t)b*NKPAD + t0*128 + tid;
        CP4(dstbase + 35840u + (uint32_t)(tid*4), src);
    }
    CP_COMMIT();
}

__global__ __launch_bounds__(256,2) void attn_mma(const unsigned* __restrict__ mask) {
    extern __shared__ __align__(128) char sm[];
    uint32_t sb = smem_u32(sm);
    int tid = threadIdx.x, wid = tid >> 5, lane = tid & 31;
    int m0 = blockIdx.x*128, h = blockIdx.y, b = blockIdx.z;
    int r16 = lane & 15, c8 = (lane >> 4) << 3, tt = lane & 15;

    // ---- stage Q (fp16) into stage-0 Kf region, pull frags to regs ----
#pragma unroll
    for (int rep = 0; rep < 4; rep++) {
        int idx = rep*256 + tid;
        int row = idx >> 3, ch = idx & 7;
        const half* src = g_qf + ((size_t)(b*NN + m0 + row))*DIMX + h*DHD + ch*8;
        *reinterpret_cast<uint4*>(sm + row*144 + ch*16) = *reinterpret_cast<const uint4*>(src);
    }
    __syncthreads();
    uint32_t qf[4][4];
#pragma unroll
    for (int k = 0; k < 4; k++)
        ldsm4(qf[k], sb + (uint32_t)((wid*16 + r16)*144 + (k*16 + c8)*2));
    __syncthreads();

    float o[8][4];
#pragma unroll
    for (int n = 0; n < 8; n++)
#pragma unroll
        for (int j = 0; j < 4; j++) o[n][j] = 0.f;
    float lsum0 = 0.f, lsum1 = 0.f;

    attn_issue(sb, b, 0, tid);

    for (int t0 = 0; t0 < NKPAD/128; t0++) {
        uint32_t stb = sb + (uint32_t)(t0 & 1)*STG;
        if (t0 < NKPAD/128 - 1) {
            attn_issue(sb + (uint32_t)((t0+1) & 1)*STG, b, t0+1, tid);
            CP_WAIT1();
        } else {
            CP_WAIT0();
        }
        __syncthreads();
        const float* msk = reinterpret_cast<const float*>(sm + (t0 & 1)*STG + 35840);

        // two half-tiles of 64 keys: keeps s footprint at 32 regs
#pragma unroll
        for (int hf = 0; hf < 2; hf++) {
            // ---- S = Q K^T (single fp16 term) for keys hf*64..hf*64+63 ----
            float s[8][4];
#pragma unroll
            for (int n = 0; n < 8; n++)
#pragma unroll
                for (int j = 0; j < 4; j++) s[n][j] = 0.f;
#pragma unroll
            for (int k = 0; k < 4; k++) {
#pragma unroll
                for (int nf = 0; nf < 8; nf++) {
                    uint32_t kb[2];
                    ldsm2(kb, stb + (uint32_t)((hf*64 + nf*8 + (tt & 7))*144 + (k*16 + ((tt >> 3) << 3))*2));
                    mma_f16(s[nf], qf[k], kb);
                }
            }

            // ---- softmax (MUFU exp; no max subtraction) ----
#pragma unroll
            for (int nf = 0; nf < 8; nf++) {
                int colb = hf*64 + nf*8 + 2*(lane & 3);
                float m0f = msk[colb], m1f = msk[colb + 1];
                float p0 = __expf(s[nf][0]) * m0f;
                float p1 = __expf(s[nf][1]) * m1f;
                float p2 = __expf(s[nf][2]) * m0f;
                float p3 = __expf(s[nf][3]) * m1f;
                s[nf][0] = p0; s[nf][1] = p1; s[nf][2] = p2; s[nf][3] = p3;
                lsum0 += p0 + p1; lsum1 += p2 + p3;
            }

            // ---- O += P V (single fp16 term), kt covers this half's keys ----
#pragma unroll
            for (int j = 0; j < 4; j++) {
                int kt = hf*4 + j;
                uint32_t ph[4];
                ph[0] = packh2(s[2*j  ][0], s[2*j  ][1]);
                ph[1] = packh2(s[2*j  ][2], s[2*j  ][3]);
                ph[2] = packh2(s[2*j+1][0], s[2*j+1][1]);
                ph[3] = packh2(s[2*j+1][2], s[2*j+1][3]);
#pragma unroll
                for (int nf = 0; nf < 8; nf++) {
                    uint32_t vf[2];
                    ldsm2(vf, stb + 18432 + (uint32_t)((nf*8 + (tt & 7))*272 + (kt*16 + ((tt >> 3) << 3))*2));
                    mma_f16(o[nf], ph, vf);
                }
            }
        }
        __syncthreads();
    }

    // ---- finalize ----
    lsum0 += __shfl_xor_sync(0xffffffffu, lsum0, 1);
    lsum0 += __shfl_xor_sync(0xffffffffu, lsum0, 2);
    lsum1 += __shfl_xor_sync(0xffffffffu, lsum1, 1);
    lsum1 += __shfl_xor_sync(0xffffffffu, lsum1, 2);
    float inv0 = 1.f / lsum0, inv1 = 1.f / lsum1;
    size_t rowA = (size_t)(b*NN + m0 + wid*16 + (lane >> 2));
    size_t rowB = rowA + 8;
    int colb = h*DHD + 2*(lane & 3);
#pragma unroll
    for (int nf = 0; nf < 8; nf++) {
        int nc = colb + nf*8;
        uint32_t hw, lw;
        splitpack(o[nf][0]*inv0, o[nf][1]*inv0, hw, lw);
        *reinterpret_cast<uint32_t*>(g_ao_hi + rowA*DIMX + nc) = hw;
        *reinterpret_cast<uint32_t*>(g_ao_lo + rowA*DIMX + nc) = lw;
        splitpack(o[nf][2]*inv1, o[nf][3]*inv1, hw, lw);
        *reinterpret_cast<uint32_t*>(g_ao_hi + rowB*DIMX + nc) = hw;
        *reinterpret_cast<uint32_t*>(g_ao_lo + rowB*DIMX + nc) = lw;
    }
}

// ---------------- launch ----------------------------------------------------
extern "C" void kernel_launch(void* const* d_in, const int* in_sizes, int n_in,
                              void* d_out, int out_size) {
    const float*    x      = (const float*)d_in[0];
    const unsigned* mask   = (const unsigned*)d_in[1];
    const float*    gamma  = (const float*)d_in[2];
    const float*    Wq     = (const float*)d_in[3];
    const float*    Wkv    = (const float*)d_in[4];
    const float*    nkv    = (const float*)d_in[5];
    const float*    Wout   = (const float*)d_in[6];
    const float*    ogamma = (const float*)d_in[7];
    float*          out    = (float*)d_out;

    float *o2;
    bf16 *xnh, *xnl, *wqh, *wql, *wkh, *wkl, *woh, *wol, *aoh, *aol;
    cudaGetSymbolAddress((void**)&o2,  g_o2);
    cudaGetSymbolAddress((void**)&xnh, g_xn_hi); cudaGetSymbolAddress((void**)&xnl, g_xn_lo);
    cudaGetSymbolAddress((void**)&wqh, g_wq_hi); cudaGetSymbolAddress((void**)&wql, g_wq_lo);
    cudaGetSymbolAddress((void**)&wkh, g_wk_hi); cudaGetSymbolAddress((void**)&wkl, g_wk_lo);
    cudaGetSymbolAddress((void**)&woh, g_wo_hi); cudaGetSymbolAddress((void**)&wol, g_wo_lo);
    cudaGetSymbolAddress((void**)&aoh, g_ao_hi); cudaGetSymbolAddress((void**)&aol, g_ao_lo);
    cudaFuncSetAttribute(attn_mma, cudaFuncAttributeMaxDynamicSharedMemorySize, ATTN_SMEM);

    ln_k<1><<<MTOT, 128>>>(x, gamma, nullptr, xnh, xnl);
    tsplit_k<<<dim3(16,16), dim3(32,8)>>>(Wq,   wqh, wql, 512);
    tsplit_k<<<dim3(4, 16), dim3(32,8)>>>(Wkv,  wkh, wkl, 128);
    tsplit_k<<<dim3(16,16), dim3(32,8)>>>(Wout, woh, wol, 512);
    kvinit_k<<<255, 256>>>(nkv, mask);
    gemm_mma<1><<<dim3(4,64), 256>>>(xnh, xnl, wqh, wql, nullptr);
    gemm_mma<2><<<dim3(1,64), 256>>>(xnh, xnl, wkh, wkl, nullptr);
    attn_mma<<<dim3(16,8,4), 256, ATTN_SMEM>>>(mask);
    gemm_mma<0><<<dim3(4,64), 256>>>(aoh, aol, woh, wol, o2);
    ln_k<0><<<MTOT, 128>>>(o2, ogamma, out, nullptr, nullptr);
}